// round 1
// baseline (speedup 1.0000x reference)
#include <cuda_runtime.h>

#define NSTR   4
#define T_LEN  8192
#define D_HID  2048
#define ND     8192        // NSTR * D_HID
#define NOUT   24          // 4 pre + 4 post + 16 res
#define NACC   25          // + sumsq
#define ROWS   32          // rows per CTA (one per lane)
#define KC     64          // K elements staged per tile per warp
#define NP     (KC/2)      // 32 pairs
#define WST    52          // smem floats per pair-row (16B aligned, low conflict)
#define NTILES (D_HID/KC)  // 32

__device__ __forceinline__ void fma2(unsigned long long &acc,
                                     unsigned long long a,
                                     unsigned long long b) {
    // packed f32x2 FMA: 2 fp32 FMAs per instruction (FFMA2)
    asm("fma.rn.f32x2 %0, %1, %2, %0;" : "+l"(acc) : "l"(a), "l"(b));
}

__device__ __forceinline__ float lo32(unsigned long long v) {
    return __uint_as_float((unsigned)(v & 0xffffffffull));
}
__device__ __forceinline__ float hi32(unsigned long long v) {
    return __uint_as_float((unsigned)(v >> 32));
}

__global__ __launch_bounds__(128, 2)
void mhc_main(const float* __restrict__ stream,
              const float* __restrict__ Wpre,
              const float* __restrict__ Wpost,
              const float* __restrict__ Wres,
              const float* __restrict__ bpre,
              const float* __restrict__ bpost,
              const float* __restrict__ bres,
              const float* __restrict__ apre_p,
              const float* __restrict__ apost_p,
              const float* __restrict__ ares_p,
              float* __restrict__ out)
{
    // per-warp weight tile, pair-interleaved: ws[w][p*WST + 2k + h] = W[k][kbase+2p+h]
    __shared__ float ws[4][NP * WST];   // 4 * 32 * 52 * 4B = 26,624 B

    const int lane = threadIdx.x & 31;
    const int w    = threadIdx.x >> 5;          // warp index == stream segment
    const int t    = blockIdx.x * ROWS + lane;  // this lane's row

    // x[t, w*2048 + j] = stream[w, t, j]
    const float* xrow = stream + (size_t)w * T_LEN * D_HID + (size_t)t * D_HID;

    unsigned long long acc[NACC];
#pragma unroll
    for (int i = 0; i < NACC; i++) acc[i] = 0ull;

    float* wsw = ws[w];
    const int segoff = w * D_HID;

    for (int tile = 0; tile < NTILES; ++tile) {
        const int kbase = tile * KC;

        __syncwarp();
        // stage 24 x 64 weights, gmem-coalesced, pair-interleaved into smem
#pragma unroll 4
        for (int idx = lane; idx < NOUT * KC; idx += 32) {
            const int k  = idx >> 6;        // output row 0..23
            const int jj = idx & 63;        // k-offset within tile
            const float* src;
            if (k < 4)      src = Wpre  + k * ND;
            else if (k < 8) src = Wpost + (k - 4) * ND;
            else            src = Wres  + (k - 8) * ND;
            const float v = src[segoff + kbase + jj];
            wsw[(jj >> 1) * WST + 2 * k + (jj & 1)] = v;
        }
        __syncwarp();

        const ulonglong2* xp = reinterpret_cast<const ulonglong2*>(xrow + kbase);
#pragma unroll
        for (int pp = 0; pp < NP / 2; ++pp) {
            const ulonglong2 xv = xp[pp];   // 4 consecutive x values (2 pairs)
            {
                const ulonglong2* wr =
                    reinterpret_cast<const ulonglong2*>(wsw + (2 * pp) * WST);
#pragma unroll
                for (int m = 0; m < 12; m++) {
                    const ulonglong2 wv = wr[m];   // LDS.128 broadcast: k=2m,2m+1
                    fma2(acc[2 * m],     xv.x, wv.x);
                    fma2(acc[2 * m + 1], xv.x, wv.y);
                }
                fma2(acc[24], xv.x, xv.x);         // sumsq
            }
            {
                const ulonglong2* wr =
                    reinterpret_cast<const ulonglong2*>(wsw + (2 * pp + 1) * WST);
#pragma unroll
                for (int m = 0; m < 12; m++) {
                    const ulonglong2 wv = wr[m];
                    fma2(acc[2 * m],     xv.y, wv.x);
                    fma2(acc[2 * m + 1], xv.y, wv.y);
                }
                fma2(acc[24], xv.y, xv.y);
            }
        }
    }

    // merge packed halves
    float resv[NACC];
#pragma unroll
    for (int i = 0; i < NACC; i++) resv[i] = lo32(acc[i]) + hi32(acc[i]);

    // cross-warp reduction buffer overlaid on this warp's OWN weight region
    // (32 rows * 26 floats = 832 <= NP*WST = 1664)
    __syncwarp();
#pragma unroll
    for (int i = 0; i < NACC; i++) wsw[lane * 26 + i] = resv[i];
    __syncthreads();

    if (w == 0) {
        float v[NACC];
#pragma unroll
        for (int i = 0; i < NACC; i++)
            v[i] = ws[0][lane * 26 + i] + ws[1][lane * 26 + i] +
                   ws[2][lane * 26 + i] + ws[3][lane * 26 + i];

        // RMSNorm scale applied post-hoc (dots are linear in x)
        const float rn = rsqrtf(v[24] * (1.0f / (float)ND) + 1e-8f);

        const float apre  = *apre_p;
        const float apost = *apost_p;
        const float ares  = *ares_p;

        float* outres  = out;                                // (T,4,4)
        float* outpre  = out + (size_t)T_LEN * 16;           // (T,4)
        float* outpost = out + (size_t)T_LEN * 16 + (size_t)T_LEN * 4;

#pragma unroll
        for (int k = 0; k < 4; k++) {
            const float z = apre * v[k] * rn + bpre[k];
            outpre[(size_t)t * 4 + k] = 1.0f / (1.0f + expf(-z));
        }
#pragma unroll
        for (int k = 0; k < 4; k++) {
            const float z = apost * v[4 + k] * rn + bpost[k];
            outpost[(size_t)t * 4 + k] = 2.0f / (1.0f + expf(-z));
        }

        float M[16];
#pragma unroll
        for (int i = 0; i < 16; i++)
            M[i] = expf(ares * v[8 + i] * rn + bres[i]);

        // Sinkhorn-Knopp, 20 iterations (row then column normalize)
        for (int it = 0; it < 20; it++) {
#pragma unroll
            for (int a = 0; a < 4; a++) {
                const float s = M[4*a] + M[4*a+1] + M[4*a+2] + M[4*a+3];
                const float r = 1.0f / s;
                M[4*a] *= r; M[4*a+1] *= r; M[4*a+2] *= r; M[4*a+3] *= r;
            }
#pragma unroll
            for (int b = 0; b < 4; b++) {
                const float s = M[b] + M[4+b] + M[8+b] + M[12+b];
                const float r = 1.0f / s;
                M[b] *= r; M[4+b] *= r; M[8+b] *= r; M[12+b] *= r;
            }
        }
#pragma unroll
        for (int i = 0; i < 16; i++) outres[(size_t)t * 16 + i] = M[i];
    }
}

extern "C" void kernel_launch(void* const* d_in, const int* in_sizes, int n_in,
                              void* d_out, int out_size) {
    const float* stream = (const float*)d_in[0];
    const float* Wpre   = (const float*)d_in[1];
    const float* Wpost  = (const float*)d_in[2];
    const float* Wres   = (const float*)d_in[3];
    const float* bpre   = (const float*)d_in[4];
    const float* bpost  = (const float*)d_in[5];
    const float* bres   = (const float*)d_in[6];
    const float* apre   = (const float*)d_in[7];
    const float* apost  = (const float*)d_in[8];
    const float* ares   = (const float*)d_in[9];

    mhc_main<<<T_LEN / ROWS, 128>>>(stream, Wpre, Wpost, Wres,
                                    bpre, bpost, bres,
                                    apre, apost, ares,
                                    (float*)d_out);
}

// round 2
// speedup vs baseline: 4.1968x; 4.1968x over previous
#include <cuda_runtime.h>

#define NSTR   4
#define T_LEN  8192
#define D_HID  2048
#define ND     8192
#define NOUT   24
#define NACC   25
#define KQ     4                 // K-split per segment -> 4x grid
#define KCHUNK (D_HID / KQ)      // 512
#define KC     64                // K per staged tile
#define NTILES (KCHUNK / KC)     // 8
#define NSTEP  (KC / 4)          // 16 x-quads per tile

// partial results: [kq][acc][row]  (row-major innermost for coalesced st/ld)
__device__ float g_scratch[KQ][NACC][T_LEN];   // 3.2 MB static

__device__ __forceinline__ void fma2(unsigned long long &acc,
                                     unsigned long long a,
                                     unsigned long long b) {
    asm("fma.rn.f32x2 %0, %1, %2, %0;" : "+l"(acc) : "l"(a), "l"(b));
}
__device__ __forceinline__ float lo32(unsigned long long v) {
    return __uint_as_float((unsigned)(v & 0xffffffffull));
}
__device__ __forceinline__ float hi32(unsigned long long v) {
    return __uint_as_float((unsigned)(v >> 32));
}
__device__ __forceinline__ void cp16(unsigned dst, const float* src) {
    asm volatile("cp.async.cg.shared.global [%0], [%1], 16;\n"
                 :: "r"(dst), "l"(src) : "memory");
}
__device__ __forceinline__ void cp_commit() {
    asm volatile("cp.async.commit_group;\n" ::: "memory");
}
template <int N>
__device__ __forceinline__ void cp_wait() {
    asm volatile("cp.async.wait_group %0;\n" :: "n"(N) : "memory");
}

__global__ __launch_bounds__(128, 4)
void mhc_part(const float* __restrict__ stream,
              const float* __restrict__ Wpre,
              const float* __restrict__ Wpost,
              const float* __restrict__ Wres)
{
    // per-warp double-buffered weight tiles: [warp][buf][24 rows][64 k] (256B rows)
    __shared__ __align__(16) float ws[4][2][NOUT][KC];   // 49,152 B

    const int lane   = threadIdx.x & 31;
    const int w      = threadIdx.x >> 5;        // stream segment
    const int rowblk = blockIdx.x & 255;
    const int kq     = blockIdx.x >> 8;
    const int t      = rowblk * 32 + lane;

    const float* xrow = stream + ((size_t)w * T_LEN + t) * D_HID + kq * KCHUNK;

    // staging lane pattern: lane handles rows j = 2r + h, 16B chunk (lane&15)
    const int h    = lane >> 4;
    const int offf = (lane & 15) * 4;                       // float offset in row
    const size_t coff = (size_t)w * D_HID + (size_t)kq * KCHUNK + h * (size_t)ND + offf;

    unsigned ws_u32 = (unsigned)__cvta_generic_to_shared(&ws[w][0][0][0]);

    // ---- stage one tile (24 rows x 64 floats) into buffer b via cp.async ----
    auto stage = [&](int tile, int b) {
        const unsigned dbase = ws_u32 + (unsigned)(b * NOUT * KC + h * KC + offf) * 4u;
        const size_t    goff = coff + (size_t)tile * KC;
#pragma unroll
        for (int r = 0; r < 12; r++) {
            const float* src;
            if (r < 2)      src = Wpre  + (size_t)(2 * r)     * ND + goff;
            else if (r < 4) src = Wpost + (size_t)(2 * r - 4) * ND + goff;
            else            src = Wres  + (size_t)(2 * r - 8) * ND + goff;
            cp16(dbase + (unsigned)(2 * r * KC) * 4u, src);
        }
        cp_commit();
    };

    unsigned long long acc[NACC];
#pragma unroll
    for (int i = 0; i < NACC; i++) acc[i] = 0ull;

    stage(0, 0);
    int buf = 0;

    for (int tile = 0; tile < NTILES; ++tile) {
        if (tile + 1 < NTILES) { stage(tile + 1, buf ^ 1); cp_wait<1>(); }
        else                   { cp_wait<0>(); }
        __syncwarp();

        const ulonglong2* xp =
            reinterpret_cast<const ulonglong2*>(xrow + tile * KC);
        const float* wb = &ws[w][buf][0][0];

#pragma unroll
        for (int p = 0; p < NSTEP; ++p) {
            const ulonglong2 xv = xp[p];          // 4 consecutive x (2 packed pairs)
#pragma unroll
            for (int j = 0; j < NOUT; ++j) {
                const ulonglong2 wv =
                    *reinterpret_cast<const ulonglong2*>(wb + j * KC + p * 4);
                fma2(acc[j], xv.x, wv.x);
                fma2(acc[j], xv.y, wv.y);
            }
            fma2(acc[24], xv.x, xv.x);
            fma2(acc[24], xv.y, xv.y);
        }
        __syncwarp();
        buf ^= 1;
    }

    // merge packed halves -> 25 scalars per lane (one row each)
    float resv[NACC];
#pragma unroll
    for (int i = 0; i < NACC; i++) resv[i] = lo32(acc[i]) + hi32(acc[i]);

    // cross-warp reduction through this warp's own smem region
    float* redw = &ws[w][0][0][0];          // 32*26 = 832 floats <= 3072
    __syncwarp();
#pragma unroll
    for (int i = 0; i < NACC; i++) redw[lane * 26 + i] = resv[i];
    __syncthreads();

    if (w == 0) {
#pragma unroll
        for (int i = 0; i < NACC; i++) {
            const float v = ws[0][0][0][lane * 26 + i] + ws[1][0][0][lane * 26 + i]
                          + ws[2][0][0][lane * 26 + i] + ws[3][0][0][lane * 26 + i];
            g_scratch[kq][i][t] = v;        // coalesced across lanes
        }
    }
}

__global__ void mhc_epilogue(const float* __restrict__ bpre,
                             const float* __restrict__ bpost,
                             const float* __restrict__ bres,
                             const float* __restrict__ apre_p,
                             const float* __restrict__ apost_p,
                             const float* __restrict__ ares_p,
                             float* __restrict__ out)
{
    const int t = blockIdx.x * 32 + threadIdx.x;

    float v[NACC];
#pragma unroll
    for (int i = 0; i < NACC; i++)
        v[i] = g_scratch[0][i][t] + g_scratch[1][i][t]
             + g_scratch[2][i][t] + g_scratch[3][i][t];

    const float rn = rsqrtf(v[24] * (1.0f / (float)ND) + 1e-8f);

    const float apre  = *apre_p;
    const float apost = *apost_p;
    const float ares  = *ares_p;

    float* outres  = out;                                  // (T,4,4)
    float* outpre  = out + (size_t)T_LEN * 16;             // (T,4)
    float* outpost = out + (size_t)T_LEN * 20;             // (T,4)

#pragma unroll
    for (int k = 0; k < 4; k++) {
        const float z = apre * v[k] * rn + bpre[k];
        outpre[(size_t)t * 4 + k] = 1.0f / (1.0f + expf(-z));
    }
#pragma unroll
    for (int k = 0; k < 4; k++) {
        const float z = apost * v[4 + k] * rn + bpost[k];
        outpost[(size_t)t * 4 + k] = 2.0f / (1.0f + expf(-z));
    }

    float M[16];
#pragma unroll
    for (int i = 0; i < 16; i++)
        M[i] = expf(ares * v[8 + i] * rn + bres[i]);

    for (int it = 0; it < 20; it++) {
#pragma unroll
        for (int a = 0; a < 4; a++) {
            const float r = 1.0f / (M[4*a] + M[4*a+1] + M[4*a+2] + M[4*a+3]);
            M[4*a] *= r; M[4*a+1] *= r; M[4*a+2] *= r; M[4*a+3] *= r;
        }
#pragma unroll
        for (int b = 0; b < 4; b++) {
            const float r = 1.0f / (M[b] + M[4+b] + M[8+b] + M[12+b]);
            M[b] *= r; M[4+b] *= r; M[8+b] *= r; M[12+b] *= r;
        }
    }
#pragma unroll
    for (int i = 0; i < 16; i++) outres[(size_t)t * 16 + i] = M[i];
}

extern "C" void kernel_launch(void* const* d_in, const int* in_sizes, int n_in,
                              void* d_out, int out_size) {
    const float* stream = (const float*)d_in[0];
    const float* Wpre   = (const float*)d_in[1];
    const float* Wpost  = (const float*)d_in[2];
    const float* Wres   = (const float*)d_in[3];
    const float* bpre   = (const float*)d_in[4];
    const float* bpost  = (const float*)d_in[5];
    const float* bres   = (const float*)d_in[6];
    const float* apre   = (const float*)d_in[7];
    const float* apost  = (const float*)d_in[8];
    const float* ares   = (const float*)d_in[9];

    mhc_part<<<256 * KQ, 128>>>(stream, Wpre, Wpost, Wres);
    mhc_epilogue<<<T_LEN / 32, 32>>>(bpre, bpost, bres, apre, apost, ares,
                                     (float*)d_out);
}